// round 16
// baseline (speedup 1.0000x reference)
#include <cuda_runtime.h>
#include <cstdint>

#define B  8
#define L  30
#define D  512
#define NS 21
#define NI 8

// ---------------- scratch (device globals; no allocation) ----------------
__device__ float g_wc[B*L*NS];        // wc[b,l,s]
__device__ float g_aw[B*L];           // a_words[b,l]
__device__ float g_wsum[B*NS];        // weighted_c[b,s]
__device__ float g_aslots[B*NS];      // a_slots[b,s]
__device__ float g_aslots_sum[B];
__device__ float g_part[L*B*NS*D];    // partial u accumulators per l  (10.3 MB)
__device__ float g_uslots[B*NS*D];    // u_slots[b,s,k]
__device__ float g_wc2[B*NS*NI];      // wc2[b,s,i]
__device__ float g_wc2sum[B*NI];      // weighted_c2[b,i]
__device__ int   g_maxidx[B];
__device__ float g_cspart[16*NS*NI*D];// colsum j-chunk partials (5.5 MB, L2-resident)

// ---------------- f32x2 packed-FMA helpers (sm_103a) ----------------
#define UNPACK2(a, b, i) asm("mov.b64 {%0, %1}, %2;" : "=f"(a), "=f"(b) : "l"(i))
#define FMA2(acc, a, b) asm("fma.rn.f32x2 %0, %1, %2, %3;" : "=l"(acc) : "l"(a), "l"(b), "l"(acc))
#define CP16(dst, src) asm volatile("cp.async.cg.shared.global [%0], [%1], 16;" :: "r"(dst), "l"(src))

// kC dynamic smem: x tile (B*D floats) + 8 warps * 3 stages * 1024 floats (4KB panels)
#define KC_STAGE_F 1024
#define KC_SMEM ((B*D + 8*3*KC_STAGE_F) * 4)   // 16KB + 96KB = 112KB  (2 CTA/SM)

// ============ Kernel A: word->slot routing (logits, softmax, wc, slots) ============
__global__ void kA(const float* __restrict__ x, const float* __restrict__ wr,
                   float* __restrict__ out) {
    int b = blockIdx.x / L, l = blockIdx.x % L;
    __shared__ float xs[D];
    __shared__ float logits[NS];
    __shared__ float red[4];
    const float* xp = x + (size_t)(b*L + l)*D;
    int tid = threadIdx.x;              // 128 threads
    float psum = 0.f;
    for (int j = tid; j < D; j += 128) { float v = xp[j]; xs[j] = v; psum += v; }
    for (int o = 16; o; o >>= 1) psum += __shfl_xor_sync(~0u, psum, o);
    if ((tid & 31) == 0) red[tid >> 5] = psum;
    __syncthreads();
    float aw = (red[0] + red[1] + red[2] + red[3]) * (1.f / (float)D);
    int w = tid >> 5, lane = tid & 31;
    for (int n = w; n < NS; n += 4) {
        const float* wrow = wr + (size_t)(l*NS + n)*D;
        float acc = 0.f;
        for (int j = lane; j < D; j += 32) acc += wrow[j] * xs[j];
        for (int o = 16; o; o >>= 1) acc += __shfl_xor_sync(~0u, acc, o);
        if (lane == 0) logits[n] = acc;
    }
    __syncthreads();
    if (tid == 0) {
        float mx = logits[0]; int am = 0;
        for (int n = 1; n < NS; n++) if (logits[n] > mx) { mx = logits[n]; am = n; }
        float e[NS], se = 0.f;
        for (int n = 0; n < NS; n++) { e[n] = expf(logits[n] - mx); se += e[n]; }
        float inv = aw / se;
        for (int n = 0; n < NS; n++) g_wc[(b*L + l)*NS + n] = e[n] * inv;
        g_aw[b*L + l] = aw;
        out[b*L + l] = (float)am;   // slots (argmax of logits == argmax of softmax)
    }
}

// ============ Kernel B: per-batch slot statistics ============
__global__ void kB() {
    int b = blockIdx.x, lane = threadIdx.x;   // 32 threads
    float wsum = 0.f;
    if (lane < NS) for (int l = 0; l < L; l++) wsum += g_wc[(b*L + l)*NS + lane];
    float awp = 0.f;
    for (int l = lane; l < L; l += 32) awp += g_aw[b*L + l];
    for (int o = 16; o; o >>= 1) awp += __shfl_xor_sync(~0u, awp, o);
    float asl = (lane < NS) ? wsum / awp : 0.f;
    float ssum = asl;
    for (int o = 16; o; o >>= 1) ssum += __shfl_xor_sync(~0u, ssum, o);
    if (lane < NS) { g_wsum[b*NS + lane] = wsum; g_aslots[b*NS + lane] = asl; }
    if (lane == 0) g_aslots_sum[b] = ssum;
}

// ============ Kernel C: pose stream — half-tile grid (R12-proven geometry) ============
// u_hat_slots[b,l,s,k] = sum_j W[l,s,k,j] * x[b,l,j]
// CTA = (s,l,kh): rows [kh*256, kh*256+256). 256 thr; warp w owns rows
// kh*256+w*32+lane. W staged in j-panels (32 rows x 32 cols = 4KB) via
// cp.async 3-stage warp-private ring, XOR-granule swizzle. 112KB smem ->
// 2 CTA/SM; SM-mate CTA hides prologue/drain. No shuffles.
__global__ __launch_bounds__(256, 2) void kC(const float* __restrict__ x,
                                             const float* __restrict__ wp) {
    extern __shared__ float sm[];
    float* xs = sm;                        // B*D floats (16 KB)
    float* wb = sm + B*D;                  // 8 warps * 3 stages * 1024 floats
    __shared__ float wcs[B];
    int blk = blockIdx.x;                  // [0, NS*L*2)
    int kh = blk & 1;
    int sl = blk >> 1;
    int s = sl / L, l = sl % L;
    int tid = threadIdx.x, w = tid >> 5, lane = tid & 31;
    const float* Wb = wp + (size_t)(l*NS + s)*D*D + (size_t)(kh*256 + w*32)*D;
    float* wbw = wb + w * (3*KC_STAGE_F);  // this warp's 3-stage ring
    const int g0 = lane & 7;

    // prologue: stage panels 0,1,2 (4KB each: 8 CP16 per lane)
    #pragma unroll
    for (int p0 = 0; p0 < 3; p0++) {
        uint32_t base = (uint32_t)__cvta_generic_to_shared(wbw + p0*KC_STAGE_F);
        #pragma unroll
        for (int it = 0; it < 8; it++) {
            int idx = lane + (it << 5);
            int r = idx >> 3, gg = idx & 7;
            const char* src = (const char*)(Wb + (size_t)r*D + p0*32) + gg*16;
            CP16(base + r*128 + ((gg ^ (r & 7)) << 4), src);
        }
        asm volatile("cp.async.commit_group;");
    }

    for (int i = tid; i < B*(D/4); i += 256) {
        int b = i >> 7, j4 = i & 127;
        ((float4*)xs)[i] = ((const float4*)(x + (size_t)(b*L + l)*D))[j4];
    }
    if (tid < B) wcs[tid] = g_wc[(tid*L + l)*NS + s];
    __syncthreads();                       // xs + wcs visible

    unsigned long long acc[8];
    #pragma unroll
    for (int b = 0; b < 8; b++) acc[b] = 0ull;

    for (int p = 0; p < 16; p++) {
        asm volatile("cp.async.wait_group 2;");  // panel p resident
        const char* Wst = (const char*)(wbw + (p%3)*KC_STAGE_F);
        #pragma unroll
        for (int st = 0; st < 8; st++) {
            ulonglong2 xv[8];
            #pragma unroll
            for (int b = 0; b < 8; b++)     // broadcast reads (1 wavefront each)
                xv[b] = *(const ulonglong2*)(xs + b*D + p*32 + st*4);
            ulonglong2 w0 = *(const ulonglong2*)(Wst + lane*128 + ((st ^ g0) << 4));
            #pragma unroll
            for (int b = 0; b < 8; b++) {
                FMA2(acc[b], w0.x, xv[b].x); FMA2(acc[b], w0.y, xv[b].y);
            }
        }
        // refill stage (p%3) with panel p+3
        if (p + 3 < 16) {
            uint32_t base = (uint32_t)__cvta_generic_to_shared(wbw + (p%3)*KC_STAGE_F);
            #pragma unroll
            for (int it = 0; it < 8; it++) {
                int idx = lane + (it << 5);
                int r = idx >> 3, gg = idx & 7;
                const char* src = (const char*)(Wb + (size_t)r*D + (p+3)*32) + gg*16;
                CP16(base + r*128 + ((gg ^ (r & 7)) << 4), src);
            }
        }
        asm volatile("cp.async.commit_group;");  // empty near tail keeps counts aligned
    }

    // epilogue: lane owns row k, all 8 batches (coalesced 128B stores)
    float* partp = g_part + (size_t)l*(B*NS*D);
    int k = kh*256 + (w << 5) + lane;
    #pragma unroll
    for (int b = 0; b < 8; b++) {
        float lo, hi; UNPACK2(lo, hi, acc[b]);
        partp[((b*NS + s) << 9) + k] = (lo + hi) * wcs[b];
    }
}

// ============ Kernel E1: FUSED u_slots reduce + intent logits + softmax ============
__global__ void kE1(const float* __restrict__ wr_si) {
    int blk = blockIdx.x;                 // [0, B*NS)
    int b = blk / NS, s = blk % NS;
    int tid = threadIdx.x;
    __shared__ float us[D];
    __shared__ float lg[NI];
    float ws = g_wsum[b*NS + s];
    #pragma unroll
    for (int kk = 0; kk < 2; kk++) {
        int k = tid + (kk << 8);
        float sum = 0.f;
        #pragma unroll
        for (int l = 0; l < L; l++)
            sum += g_part[(size_t)l*(B*NS*D) + ((size_t)(b*NS + s) << 9) + k];
        float u = sum / ws;
        us[k] = u;
        g_uslots[(size_t)(b*NS + s)*D + k] = u;
    }
    __syncthreads();
    int w = tid >> 5, lane = tid & 31;
    const float4* w4 = (const float4*)(wr_si + (size_t)(s*NI + w)*D);
    const float4* u4 = (const float4*)us;
    float acc = 0.f;
    #pragma unroll
    for (int it = 0; it < 4; it++) {
        int idx = lane + (it << 5);
        float4 a = w4[idx], xv = u4[idx];
        acc += a.x*xv.x + a.y*xv.y + a.z*xv.z + a.w*xv.w;
    }
    for (int o = 16; o; o >>= 1) acc += __shfl_xor_sync(~0u, acc, o);
    if (lane == 0) lg[w] = acc;
    __syncthreads();
    if (tid < NI) {
        float v = lg[tid];
        float m = v;
        for (int o = 4; o; o >>= 1) m = fmaxf(m, __shfl_xor_sync(0xffu, m, o));
        float e = expf(v - m);
        float se = e;
        for (int o = 4; o; o >>= 1) se += __shfl_xor_sync(0xffu, se, o);
        g_wc2[(b*NS + s)*NI + tid] = (e / se) * g_aslots[b*NS + s];
    }
}

// ============ Kernel E2: wc2sum, a_intents, argmax (first-max tie) ============
__global__ void kE2() {
    int tid = threadIdx.x;                // 256 thr; warp = batch
    int b = tid >> 5, lane = tid & 31;
    if (lane < NI) {
        float wcsum = 0.f;
        for (int s = 0; s < NS; s++) wcsum += g_wc2[(b*NS + s)*NI + lane];
        g_wc2sum[b*NI + lane] = wcsum;
        float v = wcsum / g_aslots_sum[b];
        int idx = lane;
        for (int o = 4; o; o >>= 1) {
            float ov = __shfl_xor_sync(0xffu, v, o);
            int oi = __shfl_xor_sync(0xffu, idx, o);
            if (ov > v || (ov == v && oi < idx)) { v = ov; idx = oi; }
        }
        if (lane == 0) g_maxidx[b] = idx;
    }
}

// ============ Kernel Fa1: colsum j-chunk partials (USED pairs), high parallelism ============
// partial[jo][s,i,k] = sum_{j in chunk jo} wps[s,i,j,k]
__global__ __launch_bounds__(256, 6) void kFa1(const float* __restrict__ wps) {
    int blk = blockIdx.x;                  // [0, NS*NI*16)
    int pair = blk >> 4, jo = blk & 15;
    int i = pair % NI;
    bool used = false;
    #pragma unroll
    for (int b = 0; b < B; b++) used |= (g_maxidx[b] == i);
    if (!used) return;
    int tid = threadIdx.x;                 // 256 thr: thread does k=tid and k=tid+256
    const float* Wp = wps + (size_t)pair*D*D + (size_t)jo*32*D;
    float a0 = 0.f, a1 = 0.f;
    #pragma unroll
    for (int j = 0; j < 32; j++) {
        a0 += Wp[(size_t)j*D + tid];
        a1 += Wp[(size_t)j*D + 256 + tid];
    }
    float* dst = g_cspart + ((size_t)jo*(NS*NI) + pair)*D;
    dst[tid] = a0;
    dst[tid + 256] = a1;
}

// ============ Kernel G: intents epilogue (folds colsum reduce; fixed orders) ============
// colsum[s,ii,k] = sum_{jo=0..15} cspart[jo][s,ii,k]  (same order as old kFa2)
__global__ void kG(const float* __restrict__ cls, float* __restrict__ out) {
    int t = blockIdx.x * 256 + threadIdx.x;       // [0, B*D)
    int b = t >> 9, k = t & 511;
    int ii = g_maxidx[b];
    float sum = 0.f;
    #pragma unroll
    for (int s = 0; s < NS; s++) {
        float cs = 0.f;
        #pragma unroll
        for (int jo = 0; jo < 16; jo++)
            cs += g_cspart[((size_t)jo*(NS*NI) + s*NI + ii)*D + k];
        float u  = g_uslots[(size_t)(b*NS + s)*D + k];
        float wc2s = g_wc2[(b*NS + s)*NI + ii];
        sum += cs * u * wc2s;
    }
    out[B*L + t] = cls[t] + sum / g_wc2sum[b*NI + ii];
}

// ---------------- launch ----------------
extern "C" void kernel_launch(void* const* d_in, const int* in_sizes, int n_in,
                              void* d_out, int out_size) {
    const float* x     = (const float*)d_in[0];  // token_features (B,L,D)
    const float* cls   = (const float*)d_in[1];  // cls_token (B,D)
    const float* w_rws = (const float*)d_in[2];  // w_route_ws (L,NS,D)
    const float* w_pws = (const float*)d_in[3];  // w_pose_ws (L,NS,D,D)
    const float* w_rsi = (const float*)d_in[4];  // w_route_si (NS,NI,D)
    const float* w_psi = (const float*)d_in[5];  // w_pose_si (NS,NI,D,D)
    float* out = (float*)d_out;

    static bool attr_done = false;
    if (!attr_done) {
        cudaFuncSetAttribute(kC, cudaFuncAttributeMaxDynamicSharedMemorySize, KC_SMEM);
        attr_done = true;
    }

    kA<<<B*L, 128>>>(x, w_rws, out);
    kB<<<B, 32>>>();
    kC<<<NS*L*2, 256, KC_SMEM>>>(x, w_pws);
    kE1<<<B*NS, 256>>>(w_rsi);    // fused u_slots reduce + logits + softmax
    kE2<<<1, 256>>>();
    kFa1<<<NS*NI*16, 256>>>(w_psi);
    kG<<<(B*D)/256, 256>>>(cls, out);
}

// round 17
// speedup vs baseline: 1.0395x; 1.0395x over previous
#include <cuda_runtime.h>
#include <cstdint>

#define B  8
#define L  30
#define D  512
#define NS 21
#define NI 8

// ---------------- scratch (device globals; no allocation) ----------------
__device__ float g_wc[B*L*NS];        // wc[b,l,s]
__device__ float g_aw[B*L];           // a_words[b,l]
__device__ float g_wsum[B*NS];        // weighted_c[b,s]
__device__ float g_aslots[B*NS];      // a_slots[b,s]
__device__ float g_aslots_sum[B];
__device__ float g_part[L*B*NS*D];    // partial u accumulators per l  (10.3 MB)
__device__ float g_uslots[B*NS*D];    // u_slots[b,s,k]
__device__ float g_wc2[B*NS*NI];      // wc2[b,s,i]
__device__ float g_wc2sum[B*NI];      // weighted_c2[b,i]
__device__ int   g_maxidx[B];
__device__ float g_cspart[16*NS*NI*D];// colsum j-chunk partials (5.5 MB)
__device__ float g_colsum[NS*NI*D];   // column sums of w_pose_si for used intents

// ---------------- f32x2 packed-FMA helpers (sm_103a) ----------------
#define UNPACK2(a, b, i) asm("mov.b64 {%0, %1}, %2;" : "=f"(a), "=f"(b) : "l"(i))
#define FMA2(acc, a, b) asm("fma.rn.f32x2 %0, %1, %2, %3;" : "=l"(acc) : "l"(a), "l"(b), "l"(acc))
#define CP16(dst, src) asm volatile("cp.async.cg.shared.global [%0], [%1], 16;" :: "r"(dst), "l"(src))

// kC dynamic smem: x tile (B*D floats) + 8 warps * 3 stages * 1024 floats (4KB panels)
#define KC_STAGE_F 1024
#define KC_SMEM ((B*D + 8*3*KC_STAGE_F) * 4)   // 16KB + 96KB = 112KB  (2 CTA/SM)

// ============ Kernel A: word->slot routing (logits, softmax, wc, slots) ============
__global__ void kA(const float* __restrict__ x, const float* __restrict__ wr,
                   float* __restrict__ out) {
    int b = blockIdx.x / L, l = blockIdx.x % L;
    __shared__ float xs[D];
    __shared__ float logits[NS];
    __shared__ float red[4];
    const float* xp = x + (size_t)(b*L + l)*D;
    int tid = threadIdx.x;              // 128 threads
    float psum = 0.f;
    for (int j = tid; j < D; j += 128) { float v = xp[j]; xs[j] = v; psum += v; }
    for (int o = 16; o; o >>= 1) psum += __shfl_xor_sync(~0u, psum, o);
    if ((tid & 31) == 0) red[tid >> 5] = psum;
    __syncthreads();
    float aw = (red[0] + red[1] + red[2] + red[3]) * (1.f / (float)D);
    int w = tid >> 5, lane = tid & 31;
    for (int n = w; n < NS; n += 4) {
        const float* wrow = wr + (size_t)(l*NS + n)*D;
        float acc = 0.f;
        for (int j = lane; j < D; j += 32) acc += wrow[j] * xs[j];
        for (int o = 16; o; o >>= 1) acc += __shfl_xor_sync(~0u, acc, o);
        if (lane == 0) logits[n] = acc;
    }
    __syncthreads();
    if (tid == 0) {
        float mx = logits[0]; int am = 0;
        for (int n = 1; n < NS; n++) if (logits[n] > mx) { mx = logits[n]; am = n; }
        float e[NS], se = 0.f;
        for (int n = 0; n < NS; n++) { e[n] = expf(logits[n] - mx); se += e[n]; }
        float inv = aw / se;
        for (int n = 0; n < NS; n++) g_wc[(b*L + l)*NS + n] = e[n] * inv;
        g_aw[b*L + l] = aw;
        out[b*L + l] = (float)am;   // slots (argmax of logits == argmax of softmax)
    }
}

// ============ Kernel B: per-batch slot statistics ============
__global__ void kB() {
    int b = blockIdx.x, lane = threadIdx.x;   // 32 threads
    float wsum = 0.f;
    if (lane < NS) for (int l = 0; l < L; l++) wsum += g_wc[(b*L + l)*NS + lane];
    float awp = 0.f;
    for (int l = lane; l < L; l += 32) awp += g_aw[b*L + l];
    for (int o = 16; o; o >>= 1) awp += __shfl_xor_sync(~0u, awp, o);
    float asl = (lane < NS) ? wsum / awp : 0.f;
    float ssum = asl;
    for (int o = 16; o; o >>= 1) ssum += __shfl_xor_sync(~0u, ssum, o);
    if (lane < NS) { g_wsum[b*NS + lane] = wsum; g_aslots[b*NS + lane] = asl; }
    if (lane == 0) g_aslots_sum[b] = ssum;
}

// ============ Kernel C: pose stream — half-tile grid (R12-proven geometry) ============
// u_hat_slots[b,l,s,k] = sum_j W[l,s,k,j] * x[b,l,j]
// CTA = (s,l,kh): rows [kh*256, kh*256+256). 256 thr; warp w owns rows
// kh*256+w*32+lane. W staged in j-panels (32 rows x 32 cols = 4KB) via
// cp.async 3-stage warp-private ring, XOR-granule swizzle. 112KB smem ->
// 2 CTA/SM; SM-mate CTA hides prologue/drain. No shuffles.
__global__ __launch_bounds__(256, 2) void kC(const float* __restrict__ x,
                                             const float* __restrict__ wp) {
    extern __shared__ float sm[];
    float* xs = sm;                        // B*D floats (16 KB)
    float* wb = sm + B*D;                  // 8 warps * 3 stages * 1024 floats
    __shared__ float wcs[B];
    int blk = blockIdx.x;                  // [0, NS*L*2)
    int kh = blk & 1;
    int sl = blk >> 1;
    int s = sl / L, l = sl % L;
    int tid = threadIdx.x, w = tid >> 5, lane = tid & 31;
    const float* Wb = wp + (size_t)(l*NS + s)*D*D + (size_t)(kh*256 + w*32)*D;
    float* wbw = wb + w * (3*KC_STAGE_F);  // this warp's 3-stage ring
    const int g0 = lane & 7;

    // prologue: stage panels 0,1,2 (4KB each: 8 CP16 per lane)
    #pragma unroll
    for (int p0 = 0; p0 < 3; p0++) {
        uint32_t base = (uint32_t)__cvta_generic_to_shared(wbw + p0*KC_STAGE_F);
        #pragma unroll
        for (int it = 0; it < 8; it++) {
            int idx = lane + (it << 5);
            int r = idx >> 3, gg = idx & 7;
            const char* src = (const char*)(Wb + (size_t)r*D + p0*32) + gg*16;
            CP16(base + r*128 + ((gg ^ (r & 7)) << 4), src);
        }
        asm volatile("cp.async.commit_group;");
    }

    for (int i = tid; i < B*(D/4); i += 256) {
        int b = i >> 7, j4 = i & 127;
        ((float4*)xs)[i] = ((const float4*)(x + (size_t)(b*L + l)*D))[j4];
    }
    if (tid < B) wcs[tid] = g_wc[(tid*L + l)*NS + s];
    __syncthreads();                       // xs + wcs visible

    unsigned long long acc[8];
    #pragma unroll
    for (int b = 0; b < 8; b++) acc[b] = 0ull;

    for (int p = 0; p < 16; p++) {
        asm volatile("cp.async.wait_group 2;");  // panel p resident
        const char* Wst = (const char*)(wbw + (p%3)*KC_STAGE_F);
        #pragma unroll
        for (int st = 0; st < 8; st++) {
            ulonglong2 xv[8];
            #pragma unroll
            for (int b = 0; b < 8; b++)     // broadcast reads (1 wavefront each)
                xv[b] = *(const ulonglong2*)(xs + b*D + p*32 + st*4);
            ulonglong2 w0 = *(const ulonglong2*)(Wst + lane*128 + ((st ^ g0) << 4));
            #pragma unroll
            for (int b = 0; b < 8; b++) {
                FMA2(acc[b], w0.x, xv[b].x); FMA2(acc[b], w0.y, xv[b].y);
            }
        }
        // refill stage (p%3) with panel p+3
        if (p + 3 < 16) {
            uint32_t base = (uint32_t)__cvta_generic_to_shared(wbw + (p%3)*KC_STAGE_F);
            #pragma unroll
            for (int it = 0; it < 8; it++) {
                int idx = lane + (it << 5);
                int r = idx >> 3, gg = idx & 7;
                const char* src = (const char*)(Wb + (size_t)r*D + (p+3)*32) + gg*16;
                CP16(base + r*128 + ((gg ^ (r & 7)) << 4), src);
            }
        }
        asm volatile("cp.async.commit_group;");  // empty near tail keeps counts aligned
    }

    // epilogue: lane owns row k, all 8 batches (coalesced 128B stores)
    float* partp = g_part + (size_t)l*(B*NS*D);
    int k = kh*256 + (w << 5) + lane;
    #pragma unroll
    for (int b = 0; b < 8; b++) {
        float lo, hi; UNPACK2(lo, hi, acc[b]);
        partp[((b*NS + s) << 9) + k] = (lo + hi) * wcs[b];
    }
}

// ============ Kernel E1: FUSED u_slots reduce + intent logits + softmax ============
__global__ void kE1(const float* __restrict__ wr_si) {
    int blk = blockIdx.x;                 // [0, B*NS)
    int b = blk / NS, s = blk % NS;
    int tid = threadIdx.x;
    __shared__ float us[D];
    __shared__ float lg[NI];
    float ws = g_wsum[b*NS + s];
    #pragma unroll
    for (int kk = 0; kk < 2; kk++) {
        int k = tid + (kk << 8);
        float sum = 0.f;
        #pragma unroll
        for (int l = 0; l < L; l++)
            sum += g_part[(size_t)l*(B*NS*D) + ((size_t)(b*NS + s) << 9) + k];
        float u = sum / ws;
        us[k] = u;
        g_uslots[(size_t)(b*NS + s)*D + k] = u;
    }
    __syncthreads();
    int w = tid >> 5, lane = tid & 31;
    const float4* w4 = (const float4*)(wr_si + (size_t)(s*NI + w)*D);
    const float4* u4 = (const float4*)us;
    float acc = 0.f;
    #pragma unroll
    for (int it = 0; it < 4; it++) {
        int idx = lane + (it << 5);
        float4 a = w4[idx], xv = u4[idx];
        acc += a.x*xv.x + a.y*xv.y + a.z*xv.z + a.w*xv.w;
    }
    for (int o = 16; o; o >>= 1) acc += __shfl_xor_sync(~0u, acc, o);
    if (lane == 0) lg[w] = acc;
    __syncthreads();
    if (tid < NI) {
        float v = lg[tid];
        float m = v;
        for (int o = 4; o; o >>= 1) m = fmaxf(m, __shfl_xor_sync(0xffu, m, o));
        float e = expf(v - m);
        float se = e;
        for (int o = 4; o; o >>= 1) se += __shfl_xor_sync(0xffu, se, o);
        g_wc2[(b*NS + s)*NI + tid] = (e / se) * g_aslots[b*NS + s];
    }
}

// ============ Kernel E2: wc2sum, a_intents, argmax (first-max tie) ============
__global__ void kE2() {
    int tid = threadIdx.x;                // 256 thr; warp = batch
    int b = tid >> 5, lane = tid & 31;
    if (lane < NI) {
        float wcsum = 0.f;
        for (int s = 0; s < NS; s++) wcsum += g_wc2[(b*NS + s)*NI + lane];
        g_wc2sum[b*NI + lane] = wcsum;
        float v = wcsum / g_aslots_sum[b];
        int idx = lane;
        for (int o = 4; o; o >>= 1) {
            float ov = __shfl_xor_sync(0xffu, v, o);
            int oi = __shfl_xor_sync(0xffu, idx, o);
            if (ov > v || (ov == v && oi < idx)) { v = ov; idx = oi; }
        }
        if (lane == 0) g_maxidx[b] = idx;
    }
}

// ============ Kernel Fa1: colsum j-chunk partials (USED pairs), high parallelism ============
// partial[jo][s,i,k] = sum_{j in chunk jo} wps[s,i,j,k]; >=336 active CTAs.
__global__ __launch_bounds__(256, 6) void kFa1(const float* __restrict__ wps) {
    int blk = blockIdx.x;                  // [0, NS*NI*16)
    int pair = blk >> 4, jo = blk & 15;
    int i = pair % NI;
    bool used = false;
    #pragma unroll
    for (int b = 0; b < B; b++) used |= (g_maxidx[b] == i);
    if (!used) return;
    int tid = threadIdx.x;                 // 256 thr: thread does k=tid and k=tid+256
    const float* Wp = wps + (size_t)pair*D*D + (size_t)jo*32*D;
    float a0 = 0.f, a1 = 0.f;
    #pragma unroll
    for (int j = 0; j < 32; j++) {
        a0 += Wp[(size_t)j*D + tid];
        a1 += Wp[(size_t)j*D + 256 + tid];
    }
    float* dst = g_cspart + ((size_t)jo*(NS*NI) + pair)*D;
    dst[tid] = a0;
    dst[tid + 256] = a1;
}

// ============ Kernel Fa2: fixed-order reduce of 16 j-chunk partials ============
__global__ __launch_bounds__(256, 6) void kFa2() {
    int blk = blockIdx.x;                  // [0, NS*NI*2)
    int pair = blk >> 1, kh = blk & 1;
    int i = pair % NI;
    bool used = false;
    #pragma unroll
    for (int b = 0; b < B; b++) used |= (g_maxidx[b] == i);
    if (!used) return;
    int k = kh*256 + threadIdx.x;
    float s = 0.f;
    #pragma unroll
    for (int jo = 0; jo < 16; jo++)
        s += g_cspart[((size_t)jo*(NS*NI) + pair)*D + k];
    g_colsum[(size_t)pair*D + k] = s;
}

// ============ Kernel G: intents epilogue (fixed s order, cls residual) ============
__global__ void kG(const float* __restrict__ cls, float* __restrict__ out) {
    int t = blockIdx.x * 256 + threadIdx.x;       // [0, B*D)
    int b = t >> 9, k = t & 511;
    int ii = g_maxidx[b];
    float sum = 0.f;
    #pragma unroll
    for (int s = 0; s < NS; s++) {
        float cs = g_colsum[(size_t)(s*NI + ii)*D + k];
        float u  = g_uslots[(size_t)(b*NS + s)*D + k];
        float wc2s = g_wc2[(b*NS + s)*NI + ii];
        sum += cs * u * wc2s;
    }
    out[B*L + t] = cls[t] + sum / g_wc2sum[b*NI + ii];
}

// ---------------- launch ----------------
extern "C" void kernel_launch(void* const* d_in, const int* in_sizes, int n_in,
                              void* d_out, int out_size) {
    const float* x     = (const float*)d_in[0];  // token_features (B,L,D)
    const float* cls   = (const float*)d_in[1];  // cls_token (B,D)
    const float* w_rws = (const float*)d_in[2];  // w_route_ws (L,NS,D)
    const float* w_pws = (const float*)d_in[3];  // w_pose_ws (L,NS,D,D)
    const float* w_rsi = (const float*)d_in[4];  // w_route_si (NS,NI,D)
    const float* w_psi = (const float*)d_in[5];  // w_pose_si (NS,NI,D,D)
    float* out = (float*)d_out;

    static bool attr_done = false;
    if (!attr_done) {
        cudaFuncSetAttribute(kC, cudaFuncAttributeMaxDynamicSharedMemorySize, KC_SMEM);
        attr_done = true;
    }

    kA<<<B*L, 128>>>(x, w_rws, out);
    kB<<<B, 32>>>();
    kC<<<NS*L*2, 256, KC_SMEM>>>(x, w_pws);
    kE1<<<B*NS, 256>>>(w_rsi);    // fused u_slots reduce + logits + softmax
    kE2<<<1, 256>>>();
    kFa1<<<NS*NI*16, 256>>>(w_psi);
    kFa2<<<NS*NI*2, 256>>>();
    kG<<<(B*D)/256, 256>>>(cls, out);
}